// round 1
// baseline (speedup 1.0000x reference)
#include <cuda_runtime.h>
#include <cuda_bf16.h>
#include <math.h>

// Problem constants
#define DMODEL 1024
#define TLEN   2048
#define BATCH  4
#define NHEAD  16
#define HDIM   64
#define MTOT   (BATCH*TLEN)      // 8192

// Scratch (static device globals; allocation-free rules)
__device__ float g_q [BATCH*NHEAD*TLEN*HDIM];  // [B,H,T,Hd]
__device__ float g_k [BATCH*NHEAD*TLEN*HDIM];
__device__ float g_v [BATCH*NHEAD*TLEN*HDIM];
__device__ float g_ao[BATCH*TLEN*DMODEL];      // [B,T,D]

// ---------------------------------------------------------------------------
// GEMM 1: qkv = x @ W_qkv + b_qkv, scattered to g_q/g_k/g_v in [B,H,T,Hd]
// Tiles: BM=BN=128, BK=16, 256 threads, 8x8 register tile per thread.
// ---------------------------------------------------------------------------
__global__ __launch_bounds__(256) void qkv_gemm(const float* __restrict__ A,
                                                const float* __restrict__ W,
                                                const float* __restrict__ bias) {
    const int BM = 128, BN = 128, BK = 16;
    const int N = 3 * DMODEL;
    __shared__ float As[BK * (BM + 1)];
    __shared__ float Bs[BK * BN];

    int tid = threadIdx.x;
    int ty = tid >> 4, tx = tid & 15;
    int brow = blockIdx.y * BM;
    int bcol = blockIdx.x * BN;

    int a_row = tid >> 2;      // 0..63
    int a_c4  = tid & 3;       // float4 index in row of 16
    int b_row = tid >> 5;      // 0..7
    int b_c4  = tid & 31;      // float4 index in row of 128

    float acc[8][8];
#pragma unroll
    for (int i = 0; i < 8; i++)
#pragma unroll
        for (int j = 0; j < 8; j++) acc[i][j] = 0.f;

    for (int k0 = 0; k0 < DMODEL; k0 += BK) {
#pragma unroll
        for (int h2 = 0; h2 < 2; h2++) {
            int r = a_row + h2 * 64;
            float4 av = *(const float4*)&A[(size_t)(brow + r) * DMODEL + k0 + a_c4 * 4];
            As[(a_c4 * 4 + 0) * (BM + 1) + r] = av.x;
            As[(a_c4 * 4 + 1) * (BM + 1) + r] = av.y;
            As[(a_c4 * 4 + 2) * (BM + 1) + r] = av.z;
            As[(a_c4 * 4 + 3) * (BM + 1) + r] = av.w;
            int rb = b_row + h2 * 8;
            float4 bv = *(const float4*)&W[(size_t)(k0 + rb) * N + bcol + b_c4 * 4];
            *(float4*)&Bs[rb * BN + b_c4 * 4] = bv;
        }
        __syncthreads();
#pragma unroll
        for (int kk = 0; kk < BK; kk++) {
            float a[8], b[8];
#pragma unroll
            for (int i = 0; i < 8; i++) a[i] = As[kk * (BM + 1) + ty * 8 + i];
#pragma unroll
            for (int j = 0; j < 8; j++) b[j] = Bs[kk * BN + tx * 8 + j];
#pragma unroll
            for (int i = 0; i < 8; i++)
#pragma unroll
                for (int j = 0; j < 8; j++)
                    acc[i][j] = fmaf(a[i], b[j], acc[i][j]);
        }
        __syncthreads();
    }

    // Epilogue: scatter to q/k/v in [B,H,T,Hd]
#pragma unroll
    for (int i = 0; i < 8; i++) {
        int m = brow + ty * 8 + i;
        int bb = m >> 11;          // /2048
        int t  = m & 2047;
#pragma unroll
        for (int half = 0; half < 2; half++) {
            int n0 = bcol + tx * 8 + half * 4;
            int seg = n0 >> 10;            // 0=q,1=k,2=v
            int d   = n0 & 1023;
            int h   = d >> 6;
            int hd  = d & 63;
            float* dst = (seg == 0) ? g_q : (seg == 1 ? g_k : g_v);
            float4 o;
            o.x = acc[i][half * 4 + 0] + bias[n0 + 0];
            o.y = acc[i][half * 4 + 1] + bias[n0 + 1];
            o.z = acc[i][half * 4 + 2] + bias[n0 + 2];
            o.w = acc[i][half * 4 + 3] + bias[n0 + 3];
            *(float4*)&dst[(size_t)((bb * NHEAD + h) * TLEN + t) * HDIM + hd] = o;
        }
    }
}

// ---------------------------------------------------------------------------
// Flash attention, causal. Block = (qt, bh): 64 q rows, streams 64-row KV tiles
// only for jt <= qt. 256 threads, 4x4 register tiles. Online softmax.
// Dynamic smem: Qs[64][65], Kt[64][65] (d-major), Vs[64][65], Ps[64][65].
// ---------------------------------------------------------------------------
__global__ __launch_bounds__(256) void flash_attn() {
    extern __shared__ float sm[];
    float* Qs = sm;               // [q][d], pad 65
    float* Kt = sm + 4160;        // [d][k], pad 65 (transposed)
    float* Vs = sm + 8320;        // [k][d], pad 65
    float* Ps = sm + 12480;       // [q][k], pad 65

    int tid = threadIdx.x;
    int ty = tid >> 4, tx = tid & 15;
    int qt = blockIdx.x;          // 0..31
    int bh = blockIdx.y;          // 0..63
    const float* Qg = g_q + (size_t)bh * TLEN * HDIM;
    const float* Kg = g_k + (size_t)bh * TLEN * HDIM;
    const float* Vg = g_v + (size_t)bh * TLEN * HDIM;
    int q0 = qt * 64;

    int lr  = tid >> 4;           // 0..15
    int ld4 = tid & 15;           // float4 index (d)
#pragma unroll
    for (int i = 0; i < 4; i++) {
        int qi = lr + i * 16;
        float4 qv = *(const float4*)&Qg[(size_t)(q0 + qi) * HDIM + ld4 * 4];
        Qs[qi * 65 + ld4 * 4 + 0] = qv.x * 0.125f;   // 1/sqrt(64)
        Qs[qi * 65 + ld4 * 4 + 1] = qv.y * 0.125f;
        Qs[qi * 65 + ld4 * 4 + 2] = qv.z * 0.125f;
        Qs[qi * 65 + ld4 * 4 + 3] = qv.w * 0.125f;
    }

    float mrow[4], lrow[4], acc[4][4];
#pragma unroll
    for (int i = 0; i < 4; i++) {
        mrow[i] = -1e30f; lrow[i] = 0.f;
#pragma unroll
        for (int j = 0; j < 4; j++) acc[i][j] = 0.f;
    }

    for (int jt = 0; jt <= qt; jt++) {
        __syncthreads();   // previous iteration's reads of Kt/Vs/Ps complete
        int k0 = jt * 64;
#pragma unroll
        for (int i = 0; i < 4; i++) {
            int kv = lr + i * 16;
            float4 kvv = *(const float4*)&Kg[(size_t)(k0 + kv) * HDIM + ld4 * 4];
            Kt[(ld4 * 4 + 0) * 65 + kv] = kvv.x;
            Kt[(ld4 * 4 + 1) * 65 + kv] = kvv.y;
            Kt[(ld4 * 4 + 2) * 65 + kv] = kvv.z;
            Kt[(ld4 * 4 + 3) * 65 + kv] = kvv.w;
            float4 vv = *(const float4*)&Vg[(size_t)(k0 + kv) * HDIM + ld4 * 4];
            Vs[kv * 65 + ld4 * 4 + 0] = vv.x;
            Vs[kv * 65 + ld4 * 4 + 1] = vv.y;
            Vs[kv * 65 + ld4 * 4 + 2] = vv.z;
            Vs[kv * 65 + ld4 * 4 + 3] = vv.w;
        }
        __syncthreads();

        // S = Q @ K^T (scale folded into Q)
        float s[4][4];
#pragma unroll
        for (int i = 0; i < 4; i++)
#pragma unroll
            for (int j = 0; j < 4; j++) s[i][j] = 0.f;
#pragma unroll
        for (int kk = 0; kk < 64; kk++) {
            float a[4], b[4];
#pragma unroll
            for (int i = 0; i < 4; i++) a[i] = Qs[(ty * 4 + i) * 65 + kk];
#pragma unroll
            for (int j = 0; j < 4; j++) b[j] = Kt[kk * 65 + tx * 4 + j];
#pragma unroll
            for (int i = 0; i < 4; i++)
#pragma unroll
                for (int j = 0; j < 4; j++)
                    s[i][j] = fmaf(a[i], b[j], s[i][j]);
        }
        if (jt == qt) {
#pragma unroll
            for (int i = 0; i < 4; i++)
#pragma unroll
                for (int j = 0; j < 4; j++)
                    if (tx * 4 + j > ty * 4 + i) s[i][j] = -1e30f;
        }

        // Online softmax. Row group = 16 lanes sharing ty (lane xor 1/2/4/8 stays in group).
#pragma unroll
        for (int i = 0; i < 4; i++) {
            float rm = fmaxf(fmaxf(s[i][0], s[i][1]), fmaxf(s[i][2], s[i][3]));
#pragma unroll
            for (int msk = 8; msk >= 1; msk >>= 1)
                rm = fmaxf(rm, __shfl_xor_sync(0xffffffffu, rm, msk));
            float mn = fmaxf(mrow[i], rm);
            float corr = __expf(mrow[i] - mn);
            float rs = 0.f;
#pragma unroll
            for (int j = 0; j < 4; j++) {
                s[i][j] = __expf(s[i][j] - mn);
                rs += s[i][j];
            }
#pragma unroll
            for (int msk = 8; msk >= 1; msk >>= 1)
                rs += __shfl_xor_sync(0xffffffffu, rs, msk);
            lrow[i] = lrow[i] * corr + rs;
            mrow[i] = mn;
#pragma unroll
            for (int j = 0; j < 4; j++) {
                acc[i][j] *= corr;
                Ps[(ty * 4 + i) * 65 + tx * 4 + j] = s[i][j];
            }
        }
        __syncthreads();

        // O += P @ V
#pragma unroll
        for (int kk = 0; kk < 64; kk++) {
            float a[4], b[4];
#pragma unroll
            for (int i = 0; i < 4; i++) a[i] = Ps[(ty * 4 + i) * 65 + kk];
#pragma unroll
            for (int j = 0; j < 4; j++) b[j] = Vs[kk * 65 + tx * 4 + j];
#pragma unroll
            for (int i = 0; i < 4; i++)
#pragma unroll
                for (int j = 0; j < 4; j++)
                    acc[i][j] = fmaf(a[i], b[j], acc[i][j]);
        }
    }

    // Write [B,T,D]
    int bb = bh >> 4;
    int h  = bh & 15;
#pragma unroll
    for (int i = 0; i < 4; i++) {
        int q = q0 + ty * 4 + i;
        float inv = 1.0f / lrow[i];
        float4 o = make_float4(acc[i][0] * inv, acc[i][1] * inv,
                               acc[i][2] * inv, acc[i][3] * inv);
        *(float4*)&g_ao[(size_t)(bb * TLEN + q) * DMODEL + h * HDIM + tx * 4] = o;
    }
}

// ---------------------------------------------------------------------------
// GEMM 2: out = g_ao @ W_out + b_out (plain row-major output)
// ---------------------------------------------------------------------------
__global__ __launch_bounds__(256) void out_proj_gemm(const float* __restrict__ W,
                                                     const float* __restrict__ bias,
                                                     float* __restrict__ out) {
    const int BM = 128, BN = 128, BK = 16;
    const int N = DMODEL;
    __shared__ float As[BK * (BM + 1)];
    __shared__ float Bs[BK * BN];

    int tid = threadIdx.x;
    int ty = tid >> 4, tx = tid & 15;
    int brow = blockIdx.y * BM;
    int bcol = blockIdx.x * BN;

    int a_row = tid >> 2;
    int a_c4  = tid & 3;
    int b_row = tid >> 5;
    int b_c4  = tid & 31;

    const float* A = g_ao;

    float acc[8][8];
#pragma unroll
    for (int i = 0; i < 8; i++)
#pragma unroll
        for (int j = 0; j < 8; j++) acc[i][j] = 0.f;

    for (int k0 = 0; k0 < DMODEL; k0 += BK) {
#pragma unroll
        for (int h2 = 0; h2 < 2; h2++) {
            int r = a_row + h2 * 64;
            float4 av = *(const float4*)&A[(size_t)(brow + r) * DMODEL + k0 + a_c4 * 4];
            As[(a_c4 * 4 + 0) * (BM + 1) + r] = av.x;
            As[(a_c4 * 4 + 1) * (BM + 1) + r] = av.y;
            As[(a_c4 * 4 + 2) * (BM + 1) + r] = av.z;
            As[(a_c4 * 4 + 3) * (BM + 1) + r] = av.w;
            int rb = b_row + h2 * 8;
            float4 bv = *(const float4*)&W[(size_t)(k0 + rb) * N + bcol + b_c4 * 4];
            *(float4*)&Bs[rb * BN + b_c4 * 4] = bv;
        }
        __syncthreads();
#pragma unroll
        for (int kk = 0; kk < BK; kk++) {
            float a[8], b[8];
#pragma unroll
            for (int i = 0; i < 8; i++) a[i] = As[kk * (BM + 1) + ty * 8 + i];
#pragma unroll
            for (int j = 0; j < 8; j++) b[j] = Bs[kk * BN + tx * 8 + j];
#pragma unroll
            for (int i = 0; i < 8; i++)
#pragma unroll
                for (int j = 0; j < 8; j++)
                    acc[i][j] = fmaf(a[i], b[j], acc[i][j]);
        }
        __syncthreads();
    }

#pragma unroll
    for (int i = 0; i < 8; i++) {
        int m = brow + ty * 8 + i;
#pragma unroll
        for (int half = 0; half < 2; half++) {
            int n0 = bcol + tx * 8 + half * 4;
            float4 o;
            o.x = acc[i][half * 4 + 0] + bias[n0 + 0];
            o.y = acc[i][half * 4 + 1] + bias[n0 + 1];
            o.z = acc[i][half * 4 + 2] + bias[n0 + 2];
            o.w = acc[i][half * 4 + 3] + bias[n0 + 3];
            *(float4*)&out[(size_t)m * N + n0] = o;
        }
    }
}

// ---------------------------------------------------------------------------
extern "C" void kernel_launch(void* const* d_in, const int* in_sizes, int n_in,
                              void* d_out, int out_size) {
    const float* x     = (const float*)d_in[0];
    const float* W_qkv = (const float*)d_in[1];
    const float* b_qkv = (const float*)d_in[2];
    const float* W_out = (const float*)d_in[3];
    const float* b_out = (const float*)d_in[4];
    float* out = (float*)d_out;

    // Flash kernel needs 66560 B dynamic smem (> 48KB default)
    cudaFuncSetAttribute(flash_attn, cudaFuncAttributeMaxDynamicSharedMemorySize, 66560);

    qkv_gemm<<<dim3(3 * DMODEL / 128, MTOT / 128), 256>>>(x, W_qkv, b_qkv);
    flash_attn<<<dim3(TLEN / 64, BATCH * NHEAD), 256, 66560>>>();
    out_proj_gemm<<<dim3(DMODEL / 128, MTOT / 128), 256>>>(W_out, b_out, out);
}

// round 3
// speedup vs baseline: 1.6413x; 1.6413x over previous
#include <cuda_runtime.h>
#include <cstdint>
#include <math.h>

// Problem constants
#define DMODEL 1024
#define TLEN   2048
#define BATCH  4
#define NHEAD  16
#define HDIM   64
#define MTOT   (BATCH*TLEN)      // 8192

// Scratch (static device globals; allocation-free rules)
__device__ float g_q [BATCH*NHEAD*TLEN*HDIM];  // [B,H,T,Hd]
__device__ float g_k [BATCH*NHEAD*TLEN*HDIM];
__device__ float g_v [BATCH*NHEAD*TLEN*HDIM];
__device__ float g_ao[BATCH*TLEN*DMODEL];      // [B,T,D]

// ---------------------------------------------------------------------------
// Helpers
// ---------------------------------------------------------------------------
__device__ __forceinline__ uint32_t smem_u32(const void* p) {
    uint32_t a;
    asm("{ .reg .u64 t; cvta.to.shared.u64 t, %1; cvt.u32.u64 %0, t; }"
        : "=r"(a) : "l"(p));
    return a;
}

__device__ __forceinline__ float to_tf32(float x) {
    float r;
    asm("cvt.rna.tf32.f32 %0, %1;" : "=f"(r) : "f"(x));
    return r;
}

__device__ __forceinline__ void cp16(uint32_t dst, const void* src) {
    asm volatile("cp.async.cg.shared.global [%0], [%1], 16;"
                 :: "r"(dst), "l"(src) : "memory");
}
#define CP_COMMIT() asm volatile("cp.async.commit_group;" ::: "memory")
#define CP_WAIT1()  asm volatile("cp.async.wait_group 1;" ::: "memory")
#define CP_WAIT0()  asm volatile("cp.async.wait_group 0;" ::: "memory")

// m16n8k8 row.col tf32 MMA, fp32 accumulate (legacy HMMA path — sm_103-safe)
__device__ __forceinline__ void mma_tf32(float* c, const float* a, const float* b) {
    const uint32_t* A = reinterpret_cast<const uint32_t*>(a);
    const uint32_t* B = reinterpret_cast<const uint32_t*>(b);
    asm volatile(
        "mma.sync.aligned.m16n8k8.row.col.f32.tf32.tf32.f32 "
        "{%0,%1,%2,%3}, {%4,%5,%6,%7}, {%8,%9}, {%0,%1,%2,%3};"
        : "+f"(c[0]), "+f"(c[1]), "+f"(c[2]), "+f"(c[3])
        : "r"(A[0]), "r"(A[1]), "r"(A[2]), "r"(A[3]), "r"(B[0]), "r"(B[1]));
}

// ---------------------------------------------------------------------------
// Tensor-core GEMM: C[MTOT, Ntot] = A[MTOT, 1024] @ W[1024, Ntot] + bias
// CTA tile 128x128, BK=32, 8 warps as 2(M) x 4(N), warp tile 64x32.
// cp.async double-buffered; tf32 conversion at fragment load.
// MODE 0: A = x, scatter to g_q/g_k/g_v ([B,H,T,Hd]).  MODE 1: A = g_ao -> out.
// ---------------------------------------------------------------------------
#define AS_STRIDE 36    // floats per A smem row (128 rows)
#define BS_STRIDE 136   // floats per B smem row (32 k-rows)
#define AS_BYTES  (128 * AS_STRIDE * 4)   // 18432
#define BS_BYTES  (32 * BS_STRIDE * 4)    // 17408
#define STAGE_BYTES (AS_BYTES + BS_BYTES) // 35840
#define GEMM_SMEM (2 * STAGE_BYTES)       // 71680

template<int MODE>
__global__ __launch_bounds__(256) void gemm_mma(const float* __restrict__ Ain,
                                                const float* __restrict__ W,
                                                const float* __restrict__ bias,
                                                float* __restrict__ out,
                                                int Ntot) {
    extern __shared__ char smem[];
    const uint32_t sb = smem_u32(smem);
    const int tid  = threadIdx.x;
    const int lane = tid & 31;
    const int warp = tid >> 5;
    const int mw = warp & 1;          // 0..1  (64 rows each)
    const int nw = warp >> 1;         // 0..3  (32 cols each)
    const int g   = lane >> 2;        // group id 0..7
    const int tig = lane & 3;         // thread in group 0..3
    const int brow = blockIdx.y * 128;
    const int bcol = blockIdx.x * 128;

    const float* __restrict__ A = (MODE == 1) ? (const float*)g_ao : Ain;

    // Per-thread global source coords (same every chunk, k advances)
    const int a_m  = tid >> 3;            // 0..31 (+32 per rep)  [idx = tid + r*256]
    const int a_c4 = tid & 7;
    const int b_k  = tid >> 5;            // 0..7 (+8 per rep)
    const int b_n4 = tid & 31;

    float acc[4][4][4];
#pragma unroll
    for (int i = 0; i < 4; i++)
#pragma unroll
        for (int j = 0; j < 4; j++)
#pragma unroll
            for (int q = 0; q < 4; q++) acc[i][j][q] = 0.f;

    // Issue cp.async for chunk `ic` into stage `s`
    auto issue = [&](int ic, int s) {
        const int k0 = ic * 32;
        const uint32_t As = sb + (uint32_t)s * STAGE_BYTES;
        const uint32_t Bs = As + AS_BYTES;
#pragma unroll
        for (int r = 0; r < 4; r++) {
            int m = a_m + r * 32;
            cp16(As + (uint32_t)(m * AS_STRIDE + a_c4 * 4) * 4,
                 &A[(size_t)(brow + m) * DMODEL + k0 + a_c4 * 4]);
        }
#pragma unroll
        for (int r = 0; r < 4; r++) {
            int k = b_k + r * 8;
            cp16(Bs + (uint32_t)(k * BS_STRIDE + b_n4 * 4) * 4,
                 &W[(size_t)(k0 + k) * Ntot + bcol + b_n4 * 4]);
        }
    };

    issue(0, 0);
    CP_COMMIT();

    for (int ic = 0; ic < 32; ic++) {
        const int s = ic & 1;
        if (ic + 1 < 32) {
            issue(ic + 1, s ^ 1);
            CP_COMMIT();
            CP_WAIT1();
        } else {
            CP_WAIT0();
        }
        __syncthreads();

        const float* Asf = (const float*)(smem + (size_t)s * STAGE_BYTES);
        const float* Bsf = (const float*)(smem + (size_t)s * STAGE_BYTES + AS_BYTES);

#pragma unroll
        for (int ks = 0; ks < 4; ks++) {
            const int kk = ks * 8 + tig;
            float af[4][4], bf[4][2];
#pragma unroll
            for (int mt = 0; mt < 4; mt++) {
                const int row = mw * 64 + mt * 16 + g;
                af[mt][0] = to_tf32(Asf[row * AS_STRIDE + kk]);
                af[mt][1] = to_tf32(Asf[(row + 8) * AS_STRIDE + kk]);
                af[mt][2] = to_tf32(Asf[row * AS_STRIDE + kk + 4]);
                af[mt][3] = to_tf32(Asf[(row + 8) * AS_STRIDE + kk + 4]);
            }
#pragma unroll
            for (int nt = 0; nt < 4; nt++) {
                const int col = nw * 32 + nt * 8 + g;
                bf[nt][0] = to_tf32(Bsf[kk * BS_STRIDE + col]);
                bf[nt][1] = to_tf32(Bsf[(kk + 4) * BS_STRIDE + col]);
            }
#pragma unroll
            for (int mt = 0; mt < 4; mt++)
#pragma unroll
                for (int nt = 0; nt < 4; nt++)
                    mma_tf32(acc[mt][nt], af[mt], bf[nt]);
        }
        __syncthreads();
    }

    // Epilogue: c0,c1 = (row g, cols 2tig,2tig+1); c2,c3 = (row g+8, same cols)
#pragma unroll
    for (int mt = 0; mt < 4; mt++) {
#pragma unroll
        for (int half = 0; half < 2; half++) {
            const int m = brow + mw * 64 + mt * 16 + g + half * 8;
            const int b = m >> 11, t = m & 2047;
#pragma unroll
            for (int nt = 0; nt < 4; nt++) {
                const int col = bcol + nw * 32 + nt * 8 + 2 * tig;
                float2 o;
                o.x = acc[mt][nt][half * 2 + 0] + bias[col];
                o.y = acc[mt][nt][half * 2 + 1] + bias[col + 1];
                if (MODE == 0) {
                    const int seg = col >> 10;
                    const int dc  = col & 1023;
                    const int h = dc >> 6, hd = dc & 63;
                    float* dst = (seg == 0) ? g_q : (seg == 1 ? g_k : g_v);
                    *(float2*)&dst[((size_t)((b * NHEAD + h) * TLEN + t)) * HDIM + hd] = o;
                } else {
                    *(float2*)&out[(size_t)m * DMODEL + col] = o;
                }
            }
        }
    }
}

// ---------------------------------------------------------------------------
// Flash attention, causal (fp32 — unchanged from R1; next round's target).
// ---------------------------------------------------------------------------
__global__ __launch_bounds__(256) void flash_attn() {
    extern __shared__ float sm[];
    float* Qs = sm;               // [q][d], pad 65
    float* Kt = sm + 4160;        // [d][k], pad 65 (transposed)
    float* Vs = sm + 8320;        // [k][d], pad 65
    float* Ps = sm + 12480;       // [q][k], pad 65

    int tid = threadIdx.x;
    int ty = tid >> 4, tx = tid & 15;
    int qt = blockIdx.x;
    int bh = blockIdx.y;
    const float* Qg = g_q + (size_t)bh * TLEN * HDIM;
    const float* Kg = g_k + (size_t)bh * TLEN * HDIM;
    const float* Vg = g_v + (size_t)bh * TLEN * HDIM;
    int q0 = qt * 64;

    int lr  = tid >> 4;
    int ld4 = tid & 15;
#pragma unroll
    for (int i = 0; i < 4; i++) {
        int qi = lr + i * 16;
        float4 qv = *(const float4*)&Qg[(size_t)(q0 + qi) * HDIM + ld4 * 4];
        Qs[qi * 65 + ld4 * 4 + 0] = qv.x * 0.125f;
        Qs[qi * 65 + ld4 * 4 + 1] = qv.y * 0.125f;
        Qs[qi * 65 + ld4 * 4 + 2] = qv.z * 0.125f;
        Qs[qi * 65 + ld4 * 4 + 3] = qv.w * 0.125f;
    }

    float mrow[4], lrow[4], acc[4][4];
#pragma unroll
    for (int i = 0; i < 4; i++) {
        mrow[i] = -1e30f; lrow[i] = 0.f;
#pragma unroll
        for (int j = 0; j < 4; j++) acc[i][j] = 0.f;
    }

    for (int jt = 0; jt <= qt; jt++) {
        __syncthreads();
        int k0 = jt * 64;
#pragma unroll
        for (int i = 0; i < 4; i++) {
            int kv = lr + i * 16;
            float4 kvv = *(const float4*)&Kg[(size_t)(k0 + kv) * HDIM + ld4 * 4];
            Kt[(ld4 * 4 + 0) * 65 + kv] = kvv.x;
            Kt[(ld4 * 4 + 1) * 65 + kv] = kvv.y;
            Kt[(ld4 * 4 + 2) * 65 + kv] = kvv.z;
            Kt[(ld4 * 4 + 3) * 65 + kv] = kvv.w;
            float4 vv = *(const float4*)&Vg[(size_t)(k0 + kv) * HDIM + ld4 * 4];
            Vs[kv * 65 + ld4 * 4 + 0] = vv.x;
            Vs[kv * 65 + ld4 * 4 + 1] = vv.y;
            Vs[kv * 65 + ld4 * 4 + 2] = vv.z;
            Vs[kv * 65 + ld4 * 4 + 3] = vv.w;
        }
        __syncthreads();

        float s[4][4];
#pragma unroll
        for (int i = 0; i < 4; i++)
#pragma unroll
            for (int j = 0; j < 4; j++) s[i][j] = 0.f;
#pragma unroll
        for (int kk = 0; kk < 64; kk++) {
            float a[4], bb[4];
#pragma unroll
            for (int i = 0; i < 4; i++) a[i] = Qs[(ty * 4 + i) * 65 + kk];
#pragma unroll
            for (int j = 0; j < 4; j++) bb[j] = Kt[kk * 65 + tx * 4 + j];
#pragma unroll
            for (int i = 0; i < 4; i++)
#pragma unroll
                for (int j = 0; j < 4; j++)
                    s[i][j] = fmaf(a[i], bb[j], s[i][j]);
        }
        if (jt == qt) {
#pragma unroll
            for (int i = 0; i < 4; i++)
#pragma unroll
                for (int j = 0; j < 4; j++)
                    if (tx * 4 + j > ty * 4 + i) s[i][j] = -1e30f;
        }

#pragma unroll
        for (int i = 0; i < 4; i++) {
            float rm = fmaxf(fmaxf(s[i][0], s[i][1]), fmaxf(s[i][2], s[i][3]));
#pragma unroll
            for (int msk = 8; msk >= 1; msk >>= 1)
                rm = fmaxf(rm, __shfl_xor_sync(0xffffffffu, rm, msk));
            float mn = fmaxf(mrow[i], rm);
            float corr = __expf(mrow[i] - mn);
            float rs = 0.f;
#pragma unroll
            for (int j = 0; j < 4; j++) {
                s[i][j] = __expf(s[i][j] - mn);
                rs += s[i][j];
            }
#pragma unroll
            for (int msk = 8; msk >= 1; msk >>= 1)
                rs += __shfl_xor_sync(0xffffffffu, rs, msk);
            lrow[i] = lrow[i] * corr + rs;
            mrow[i] = mn;
#pragma unroll
            for (int j = 0; j < 4; j++) {
                acc[i][j] *= corr;
                Ps[(ty * 4 + i) * 65 + tx * 4 + j] = s[i][j];
            }
        }
        __syncthreads();

#pragma unroll
        for (int kk = 0; kk < 64; kk++) {
            float a[4], bb[4];
#pragma unroll
            for (int i = 0; i < 4; i++) a[i] = Ps[(ty * 4 + i) * 65 + kk];
#pragma unroll
            for (int j = 0; j < 4; j++) bb[j] = Vs[kk * 65 + tx * 4 + j];
#pragma unroll
            for (int i = 0; i < 4; i++)
#pragma unroll
                for (int j = 0; j < 4; j++)
                    acc[i][j] = fmaf(a[i], bb[j], acc[i][j]);
        }
    }

    int bb2 = bh >> 4;
    int h  = bh & 15;
#pragma unroll
    for (int i = 0; i < 4; i++) {
        int q = q0 + ty * 4 + i;
        float inv = 1.0f / lrow[i];
        float4 o = make_float4(acc[i][0] * inv, acc[i][1] * inv,
                               acc[i][2] * inv, acc[i][3] * inv);
        *(float4*)&g_ao[(size_t)(bb2 * TLEN + q) * DMODEL + h * HDIM + tx * 4] = o;
    }
}

// ---------------------------------------------------------------------------
extern "C" void kernel_launch(void* const* d_in, const int* in_sizes, int n_in,
                              void* d_out, int out_size) {
    const float* x     = (const float*)d_in[0];
    const float* W_qkv = (const float*)d_in[1];
    const float* b_qkv = (const float*)d_in[2];
    const float* W_out = (const float*)d_in[3];
    const float* b_out = (const float*)d_in[4];
    float* out = (float*)d_out;

    cudaFuncSetAttribute(gemm_mma<0>, cudaFuncAttributeMaxDynamicSharedMemorySize, GEMM_SMEM);
    cudaFuncSetAttribute(gemm_mma<1>, cudaFuncAttributeMaxDynamicSharedMemorySize, GEMM_SMEM);
    cudaFuncSetAttribute(flash_attn, cudaFuncAttributeMaxDynamicSharedMemorySize, 66560);

    gemm_mma<0><<<dim3(3 * DMODEL / 128, MTOT / 128), 256, GEMM_SMEM>>>(
        x, W_qkv, b_qkv, nullptr, 3 * DMODEL);
    flash_attn<<<dim3(TLEN / 64, BATCH * NHEAD), 256, 66560>>>();
    gemm_mma<1><<<dim3(DMODEL / 128, MTOT / 128), 256, GEMM_SMEM>>>(
        nullptr, W_out, b_out, out, DMODEL);
}

// round 4
// speedup vs baseline: 3.1059x; 1.8924x over previous
#include <cuda_runtime.h>
#include <cstdint>
#include <math.h>

// Problem constants
#define DMODEL 1024
#define TLEN   2048
#define BATCH  4
#define NHEAD  16
#define HDIM   64
#define MTOT   (BATCH*TLEN)      // 8192

// Scratch (static device globals; allocation-free rules)
__device__ float g_q [BATCH*NHEAD*TLEN*HDIM];  // [B,H,T,Hd]
__device__ float g_k [BATCH*NHEAD*TLEN*HDIM];
__device__ float g_v [BATCH*NHEAD*TLEN*HDIM];
__device__ float g_ao[BATCH*TLEN*DMODEL];      // [B,T,D]

// ---------------------------------------------------------------------------
// Helpers
// ---------------------------------------------------------------------------
__device__ __forceinline__ uint32_t smem_u32(const void* p) {
    uint32_t a;
    asm("{ .reg .u64 t; cvta.to.shared.u64 t, %1; cvt.u32.u64 %0, t; }"
        : "=r"(a) : "l"(p));
    return a;
}

__device__ __forceinline__ float to_tf32(float x) {
    float r;
    asm("cvt.rna.tf32.f32 %0, %1;" : "=f"(r) : "f"(x));
    return r;
}

__device__ __forceinline__ void cp16(uint32_t dst, const void* src) {
    asm volatile("cp.async.cg.shared.global [%0], [%1], 16;"
                 :: "r"(dst), "l"(src) : "memory");
}
#define CP_COMMIT() asm volatile("cp.async.commit_group;" ::: "memory")
#define CP_WAIT1()  asm volatile("cp.async.wait_group 1;" ::: "memory")
#define CP_WAIT0()  asm volatile("cp.async.wait_group 0;" ::: "memory")

// m16n8k8 row.col tf32 MMA, fp32 accumulate (legacy HMMA path — sm_103-safe)
__device__ __forceinline__ void mma_tf32(float* c, const float* a, const float* b) {
    const uint32_t* A = reinterpret_cast<const uint32_t*>(a);
    const uint32_t* B = reinterpret_cast<const uint32_t*>(b);
    asm volatile(
        "mma.sync.aligned.m16n8k8.row.col.f32.tf32.tf32.f32 "
        "{%0,%1,%2,%3}, {%4,%5,%6,%7}, {%8,%9}, {%0,%1,%2,%3};"
        : "+f"(c[0]), "+f"(c[1]), "+f"(c[2]), "+f"(c[3])
        : "r"(A[0]), "r"(A[1]), "r"(A[2]), "r"(A[3]), "r"(B[0]), "r"(B[1]));
}

// ---------------------------------------------------------------------------
// Tensor-core GEMM (unchanged from R3 — passing at tensor=47%)
// ---------------------------------------------------------------------------
#define AS_STRIDE 36
#define BS_STRIDE 136
#define AS_BYTES  (128 * AS_STRIDE * 4)
#define BS_BYTES  (32 * BS_STRIDE * 4)
#define STAGE_BYTES (AS_BYTES + BS_BYTES)
#define GEMM_SMEM (2 * STAGE_BYTES)

template<int MODE>
__global__ __launch_bounds__(256) void gemm_mma(const float* __restrict__ Ain,
                                                const float* __restrict__ W,
                                                const float* __restrict__ bias,
                                                float* __restrict__ out,
                                                int Ntot) {
    extern __shared__ char smem[];
    const uint32_t sb = smem_u32(smem);
    const int tid  = threadIdx.x;
    const int lane = tid & 31;
    const int warp = tid >> 5;
    const int mw = warp & 1;
    const int nw = warp >> 1;
    const int g   = lane >> 2;
    const int tig = lane & 3;
    const int brow = blockIdx.y * 128;
    const int bcol = blockIdx.x * 128;

    const float* __restrict__ A = (MODE == 1) ? (const float*)g_ao : Ain;

    const int a_m  = tid >> 3;
    const int a_c4 = tid & 7;
    const int b_k  = tid >> 5;
    const int b_n4 = tid & 31;

    float acc[4][4][4];
#pragma unroll
    for (int i = 0; i < 4; i++)
#pragma unroll
        for (int j = 0; j < 4; j++)
#pragma unroll
            for (int q = 0; q < 4; q++) acc[i][j][q] = 0.f;

    auto issue = [&](int ic, int s) {
        const int k0 = ic * 32;
        const uint32_t As = sb + (uint32_t)s * STAGE_BYTES;
        const uint32_t Bs = As + AS_BYTES;
#pragma unroll
        for (int r = 0; r < 4; r++) {
            int m = a_m + r * 32;
            cp16(As + (uint32_t)(m * AS_STRIDE + a_c4 * 4) * 4,
                 &A[(size_t)(brow + m) * DMODEL + k0 + a_c4 * 4]);
        }
#pragma unroll
        for (int r = 0; r < 4; r++) {
            int k = b_k + r * 8;
            cp16(Bs + (uint32_t)(k * BS_STRIDE + b_n4 * 4) * 4,
                 &W[(size_t)(k0 + k) * Ntot + bcol + b_n4 * 4]);
        }
    };

    issue(0, 0);
    CP_COMMIT();

    for (int ic = 0; ic < 32; ic++) {
        const int s = ic & 1;
        if (ic + 1 < 32) {
            issue(ic + 1, s ^ 1);
            CP_COMMIT();
            CP_WAIT1();
        } else {
            CP_WAIT0();
        }
        __syncthreads();

        const float* Asf = (const float*)(smem + (size_t)s * STAGE_BYTES);
        const float* Bsf = (const float*)(smem + (size_t)s * STAGE_BYTES + AS_BYTES);

#pragma unroll
        for (int ks = 0; ks < 4; ks++) {
            const int kk = ks * 8 + tig;
            float af[4][4], bf[4][2];
#pragma unroll
            for (int mt = 0; mt < 4; mt++) {
                const int row = mw * 64 + mt * 16 + g;
                af[mt][0] = to_tf32(Asf[row * AS_STRIDE + kk]);
                af[mt][1] = to_tf32(Asf[(row + 8) * AS_STRIDE + kk]);
                af[mt][2] = to_tf32(Asf[row * AS_STRIDE + kk + 4]);
                af[mt][3] = to_tf32(Asf[(row + 8) * AS_STRIDE + kk + 4]);
            }
#pragma unroll
            for (int nt = 0; nt < 4; nt++) {
                const int col = nw * 32 + nt * 8 + g;
                bf[nt][0] = to_tf32(Bsf[kk * BS_STRIDE + col]);
                bf[nt][1] = to_tf32(Bsf[(kk + 4) * BS_STRIDE + col]);
            }
#pragma unroll
            for (int mt = 0; mt < 4; mt++)
#pragma unroll
                for (int nt = 0; nt < 4; nt++)
                    mma_tf32(acc[mt][nt], af[mt], bf[nt]);
        }
        __syncthreads();
    }

#pragma unroll
    for (int mt = 0; mt < 4; mt++) {
#pragma unroll
        for (int half = 0; half < 2; half++) {
            const int m = brow + mw * 64 + mt * 16 + g + half * 8;
            const int b = m >> 11, t = m & 2047;
#pragma unroll
            for (int nt = 0; nt < 4; nt++) {
                const int col = bcol + nw * 32 + nt * 8 + 2 * tig;
                float2 o;
                o.x = acc[mt][nt][half * 2 + 0] + bias[col];
                o.y = acc[mt][nt][half * 2 + 1] + bias[col + 1];
                if (MODE == 0) {
                    const int seg = col >> 10;
                    const int dc  = col & 1023;
                    const int h = dc >> 6, hd = dc & 63;
                    float* dst = (seg == 0) ? g_q : (seg == 1 ? g_k : g_v);
                    *(float2*)&dst[((size_t)((b * NHEAD + h) * TLEN + t)) * HDIM + hd] = o;
                } else {
                    *(float2*)&out[(size_t)m * DMODEL + col] = o;
                }
            }
        }
    }
}

// ---------------------------------------------------------------------------
// Flash attention, causal, tensor-core (m16n8k8 tf32).
// CTA: 256 threads (8 warps), 128 q rows (16/warp), KV tiles of 64.
// SMEM (floats, stride 68): Qs[128][68] Ks[64][68] Vs[64][68] Ps[128][68]
// All tiles stored pre-converted to tf32. S and O live in registers.
// ---------------------------------------------------------------------------
#define FSTRIDE 68
#define FLASH_SMEM ((128*FSTRIDE + 64*FSTRIDE + 64*FSTRIDE + 128*FSTRIDE) * 4)  // 104448

__global__ __launch_bounds__(256) void flash_attn_mma() {
    extern __shared__ float sm[];
    float* Qs = sm;                       // [128][68]
    float* Ks = sm + 128 * FSTRIDE;       // [64][68]  ([kv][hd])
    float* Vs = Ks + 64 * FSTRIDE;        // [64][68]  ([kv][hd])
    float* Ps = Vs + 64 * FSTRIDE;        // [128][68]

    const int tid  = threadIdx.x;
    const int lane = tid & 31;
    const int warp = tid >> 5;
    const int g    = lane >> 2;           // 0..7
    const int tig  = lane & 3;            // 0..3
    const int qt = (int)gridDim.x - 1 - (int)blockIdx.x;  // big tiles first
    const int bh = blockIdx.y;
    const int q0 = qt * 128;

    const float* Qg = g_q + (size_t)bh * TLEN * HDIM;
    const float* Kg = g_k + (size_t)bh * TLEN * HDIM;
    const float* Vg = g_v + (size_t)bh * TLEN * HDIM;

    // Load Q block once: scale by 1/8, convert to tf32
#pragma unroll
    for (int r = 0; r < 8; r++) {
        int idx = tid + r * 256;
        int row = idx >> 4, c4 = idx & 15;
        float4 v = *(const float4*)&Qg[(size_t)(q0 + row) * HDIM + c4 * 4];
        float4 w;
        w.x = to_tf32(v.x * 0.125f);
        w.y = to_tf32(v.y * 0.125f);
        w.z = to_tf32(v.z * 0.125f);
        w.w = to_tf32(v.w * 0.125f);
        *(float4*)&Qs[row * FSTRIDE + c4 * 4] = w;
    }

    float m0 = -1e30f, m1 = -1e30f, l0 = 0.f, l1 = 0.f;
    float o[8][4];
#pragma unroll
    for (int nt = 0; nt < 8; nt++)
#pragma unroll
        for (int q = 0; q < 4; q++) o[nt][q] = 0.f;

    const int qrow_w = q0 + warp * 16;    // warp's first q row
    const int prow   = warp * 16 + g;     // local P/Q row for this thread
    const int njt = 2 * qt + 2;

    for (int jt = 0; jt < njt; jt++) {
        __syncthreads();   // previous tile's reads of Ks/Vs done
        const int k0 = jt * 64;
#pragma unroll
        for (int r = 0; r < 4; r++) {
            int idx = tid + r * 256;
            int row = idx >> 4, c4 = idx & 15;
            float4 kv4 = *(const float4*)&Kg[(size_t)(k0 + row) * HDIM + c4 * 4];
            float4 wk;
            wk.x = to_tf32(kv4.x); wk.y = to_tf32(kv4.y);
            wk.z = to_tf32(kv4.z); wk.w = to_tf32(kv4.w);
            *(float4*)&Ks[row * FSTRIDE + c4 * 4] = wk;
            float4 vv4 = *(const float4*)&Vg[(size_t)(k0 + row) * HDIM + c4 * 4];
            float4 wv;
            wv.x = to_tf32(vv4.x); wv.y = to_tf32(vv4.y);
            wv.z = to_tf32(vv4.z); wv.w = to_tf32(vv4.w);
            *(float4*)&Vs[row * FSTRIDE + c4 * 4] = wv;
        }
        __syncthreads();

        if (qrow_w + 15 < k0) continue;   // warp entirely above diagonal

        // ----- S = Q @ K^T -----
        float s[8][4];
#pragma unroll
        for (int nt = 0; nt < 8; nt++)
#pragma unroll
            for (int q = 0; q < 4; q++) s[nt][q] = 0.f;
#pragma unroll
        for (int ks = 0; ks < 8; ks++) {
            float a[4];
            a[0] = Qs[prow * FSTRIDE + ks * 8 + tig];
            a[1] = Qs[(prow + 8) * FSTRIDE + ks * 8 + tig];
            a[2] = Qs[prow * FSTRIDE + ks * 8 + tig + 4];
            a[3] = Qs[(prow + 8) * FSTRIDE + ks * 8 + tig + 4];
#pragma unroll
            for (int nt = 0; nt < 8; nt++) {
                float b[2];
                b[0] = Ks[(nt * 8 + g) * FSTRIDE + ks * 8 + tig];
                b[1] = Ks[(nt * 8 + g) * FSTRIDE + ks * 8 + tig + 4];
                mma_tf32(s[nt], a, b);
            }
        }

        // ----- causal mask (only near diagonal) -----
        if (k0 + 63 > qrow_w) {
            const int row0 = qrow_w + g, row1 = row0 + 8;
#pragma unroll
            for (int nt = 0; nt < 8; nt++) {
                const int col = k0 + nt * 8 + 2 * tig;
                if (col     > row0) s[nt][0] = -1e30f;
                if (col + 1 > row0) s[nt][1] = -1e30f;
                if (col     > row1) s[nt][2] = -1e30f;
                if (col + 1 > row1) s[nt][3] = -1e30f;
            }
        }

        // ----- online softmax (rows g and g+8; quad = lanes sharing g) -----
        float rm0 = -1e30f, rm1 = -1e30f;
#pragma unroll
        for (int nt = 0; nt < 8; nt++) {
            rm0 = fmaxf(rm0, fmaxf(s[nt][0], s[nt][1]));
            rm1 = fmaxf(rm1, fmaxf(s[nt][2], s[nt][3]));
        }
        rm0 = fmaxf(rm0, __shfl_xor_sync(0xffffffffu, rm0, 1));
        rm0 = fmaxf(rm0, __shfl_xor_sync(0xffffffffu, rm0, 2));
        rm1 = fmaxf(rm1, __shfl_xor_sync(0xffffffffu, rm1, 1));
        rm1 = fmaxf(rm1, __shfl_xor_sync(0xffffffffu, rm1, 2));
        const float mn0 = fmaxf(m0, rm0), mn1 = fmaxf(m1, rm1);
        const float c0 = __expf(m0 - mn0), c1 = __expf(m1 - mn1);
        float rs0 = 0.f, rs1 = 0.f;
#pragma unroll
        for (int nt = 0; nt < 8; nt++) {
            float p00 = __expf(s[nt][0] - mn0);
            float p01 = __expf(s[nt][1] - mn0);
            float p10 = __expf(s[nt][2] - mn1);
            float p11 = __expf(s[nt][3] - mn1);
            rs0 += p00 + p01;
            rs1 += p10 + p11;
            float2 w0 = make_float2(to_tf32(p00), to_tf32(p01));
            float2 w1 = make_float2(to_tf32(p10), to_tf32(p11));
            *(float2*)&Ps[prow * FSTRIDE + nt * 8 + 2 * tig] = w0;
            *(float2*)&Ps[(prow + 8) * FSTRIDE + nt * 8 + 2 * tig] = w1;
            o[nt][0] *= c0; o[nt][1] *= c0;
            o[nt][2] *= c1; o[nt][3] *= c1;
        }
        rs0 += __shfl_xor_sync(0xffffffffu, rs0, 1);
        rs0 += __shfl_xor_sync(0xffffffffu, rs0, 2);
        rs1 += __shfl_xor_sync(0xffffffffu, rs1, 1);
        rs1 += __shfl_xor_sync(0xffffffffu, rs1, 2);
        l0 = l0 * c0 + rs0; m0 = mn0;
        l1 = l1 * c1 + rs1; m1 = mn1;

        __syncwarp();   // Ps rows are warp-private; order STS -> LDS

        // ----- O += P @ V -----
#pragma unroll
        for (int ks = 0; ks < 8; ks++) {
            float a[4];
            a[0] = Ps[prow * FSTRIDE + ks * 8 + tig];
            a[1] = Ps[(prow + 8) * FSTRIDE + ks * 8 + tig];
            a[2] = Ps[prow * FSTRIDE + ks * 8 + tig + 4];
            a[3] = Ps[(prow + 8) * FSTRIDE + ks * 8 + tig + 4];
#pragma unroll
            for (int nt = 0; nt < 8; nt++) {
                float b[2];
                b[0] = Vs[(ks * 8 + tig) * FSTRIDE + nt * 8 + g];
                b[1] = Vs[(ks * 8 + tig + 4) * FSTRIDE + nt * 8 + g];
                mma_tf32(o[nt], a, b);
            }
        }
    }

    // ----- normalize + write [B,T,D] -----
    const int b = bh >> 4;
    const int h = bh & 15;
    const float inv0 = 1.0f / l0, inv1 = 1.0f / l1;
    const int row0 = qrow_w + g;
#pragma unroll
    for (int nt = 0; nt < 8; nt++) {
        const int col = h * HDIM + nt * 8 + 2 * tig;
        float2 v0 = make_float2(o[nt][0] * inv0, o[nt][1] * inv0);
        float2 v1 = make_float2(o[nt][2] * inv1, o[nt][3] * inv1);
        *(float2*)&g_ao[(size_t)(b * TLEN + row0) * DMODEL + col] = v0;
        *(float2*)&g_ao[(size_t)(b * TLEN + row0 + 8) * DMODEL + col] = v1;
    }
}

// ---------------------------------------------------------------------------
extern "C" void kernel_launch(void* const* d_in, const int* in_sizes, int n_in,
                              void* d_out, int out_size) {
    const float* x     = (const float*)d_in[0];
    const float* W_qkv = (const float*)d_in[1];
    const float* b_qkv = (const float*)d_in[2];
    const float* W_out = (const float*)d_in[3];
    const float* b_out = (const float*)d_in[4];
    float* out = (float*)d_out;

    cudaFuncSetAttribute(gemm_mma<0>, cudaFuncAttributeMaxDynamicSharedMemorySize, GEMM_SMEM);
    cudaFuncSetAttribute(gemm_mma<1>, cudaFuncAttributeMaxDynamicSharedMemorySize, GEMM_SMEM);
    cudaFuncSetAttribute(flash_attn_mma, cudaFuncAttributeMaxDynamicSharedMemorySize, FLASH_SMEM);

    gemm_mma<0><<<dim3(3 * DMODEL / 128, MTOT / 128), 256, GEMM_SMEM>>>(
        x, W_qkv, b_qkv, nullptr, 3 * DMODEL);
    flash_attn_mma<<<dim3(TLEN / 128, BATCH * NHEAD), 256, FLASH_SMEM>>>();
    gemm_mma<1><<<dim3(DMODEL / 128, MTOT / 128), 256, GEMM_SMEM>>>(
        nullptr, W_out, b_out, out, DMODEL);
}

// round 5
// speedup vs baseline: 3.2506x; 1.0466x over previous
#include <cuda_runtime.h>
#include <cstdint>
#include <math.h>

// Problem constants
#define DMODEL 1024
#define TLEN   2048
#define BATCH  4
#define NHEAD  16
#define HDIM   64
#define MTOT   (BATCH*TLEN)      // 8192

// Scratch (static device globals; allocation-free rules)
__device__ float g_q [BATCH*NHEAD*TLEN*HDIM];  // [B,H,T,Hd], tf32-rounded
__device__ float g_k [BATCH*NHEAD*TLEN*HDIM];
__device__ float g_v [BATCH*NHEAD*TLEN*HDIM];
__device__ float g_ao[BATCH*TLEN*DMODEL];      // [B,T,D], tf32-rounded
__device__ float g_xr  [MTOT*DMODEL];          // tf32-rounded x
__device__ float g_wqkv[DMODEL*3*DMODEL];      // tf32-rounded W_qkv
__device__ float g_wout[DMODEL*DMODEL];        // tf32-rounded W_out

// ---------------------------------------------------------------------------
// Helpers
// ---------------------------------------------------------------------------
__device__ __forceinline__ uint32_t smem_u32(const void* p) {
    uint32_t a;
    asm("{ .reg .u64 t; cvta.to.shared.u64 t, %1; cvt.u32.u64 %0, t; }"
        : "=r"(a) : "l"(p));
    return a;
}

__device__ __forceinline__ float to_tf32(float x) {
    float r;
    asm("cvt.rna.tf32.f32 %0, %1;" : "=f"(r) : "f"(x));
    return r;
}

__device__ __forceinline__ void cp16(uint32_t dst, const void* src) {
    asm volatile("cp.async.cg.shared.global [%0], [%1], 16;"
                 :: "r"(dst), "l"(src) : "memory");
}
#define CP_COMMIT() asm volatile("cp.async.commit_group;" ::: "memory")
#define CP_WAIT1()  asm volatile("cp.async.wait_group 1;" ::: "memory")
#define CP_WAIT0()  asm volatile("cp.async.wait_group 0;" ::: "memory")

// m16n8k8 row.col tf32 MMA, fp32 accumulate
__device__ __forceinline__ void mma_tf32(float* c, const float* a, const float* b) {
    const uint32_t* A = reinterpret_cast<const uint32_t*>(a);
    const uint32_t* B = reinterpret_cast<const uint32_t*>(b);
    asm volatile(
        "mma.sync.aligned.m16n8k8.row.col.f32.tf32.tf32.f32 "
        "{%0,%1,%2,%3}, {%4,%5,%6,%7}, {%8,%9}, {%0,%1,%2,%3};"
        : "+f"(c[0]), "+f"(c[1]), "+f"(c[2]), "+f"(c[3])
        : "r"(A[0]), "r"(A[1]), "r"(A[2]), "r"(A[3]), "r"(B[0]), "r"(B[1]));
}

// ---------------------------------------------------------------------------
// Pre-pass: round an fp32 array to tf32 (read src, write dst), float4-wide.
// ---------------------------------------------------------------------------
__global__ __launch_bounds__(256) void round_tf32(const float4* __restrict__ src,
                                                  float4* __restrict__ dst, int n4) {
    int i = blockIdx.x * blockDim.x + threadIdx.x;
    if (i < n4) {
        float4 v = src[i];
        v.x = to_tf32(v.x); v.y = to_tf32(v.y);
        v.z = to_tf32(v.z); v.w = to_tf32(v.w);
        dst[i] = v;
    }
}

// ---------------------------------------------------------------------------
// Tensor-core GEMM: all inputs pre-rounded tf32; no cvt in hot loop.
// CTA tile 128x128, BK=32, 8 warps 2(M)x4(N), cp.async double-buffered.
// MODE 0: A=g_xr, W=g_wqkv; scatter tf32-rounded q/k/v.
// MODE 1: A=g_ao,  W=g_wout; write fp32 out.
// ---------------------------------------------------------------------------
#define AS_STRIDE 36
#define BS_STRIDE 136
#define AS_BYTES  (128 * AS_STRIDE * 4)
#define BS_BYTES  (32 * BS_STRIDE * 4)
#define STAGE_BYTES (AS_BYTES + BS_BYTES)
#define GEMM_SMEM (2 * STAGE_BYTES)

template<int MODE>
__global__ __launch_bounds__(256) void gemm_mma(const float* __restrict__ bias,
                                                float* __restrict__ out,
                                                int Ntot) {
    extern __shared__ char smem[];
    const uint32_t sb = smem_u32(smem);
    const int tid  = threadIdx.x;
    const int lane = tid & 31;
    const int warp = tid >> 5;
    const int mw = warp & 1;
    const int nw = warp >> 1;
    const int g   = lane >> 2;
    const int tig = lane & 3;
    const int brow = blockIdx.y * 128;
    const int bcol = blockIdx.x * 128;

    const float* __restrict__ A = (MODE == 1) ? (const float*)g_ao : (const float*)g_xr;
    const float* __restrict__ W = (MODE == 1) ? (const float*)g_wout : (const float*)g_wqkv;

    const int a_m  = tid >> 3;
    const int a_c4 = tid & 7;
    const int b_k  = tid >> 5;
    const int b_n4 = tid & 31;

    float acc[4][4][4];
#pragma unroll
    for (int i = 0; i < 4; i++)
#pragma unroll
        for (int j = 0; j < 4; j++)
#pragma unroll
            for (int q = 0; q < 4; q++) acc[i][j][q] = 0.f;

    auto issue = [&](int ic, int s) {
        const int k0 = ic * 32;
        const uint32_t As = sb + (uint32_t)s * STAGE_BYTES;
        const uint32_t Bs = As + AS_BYTES;
#pragma unroll
        for (int r = 0; r < 4; r++) {
            int m = a_m + r * 32;
            cp16(As + (uint32_t)(m * AS_STRIDE + a_c4 * 4) * 4,
                 &A[(size_t)(brow + m) * DMODEL + k0 + a_c4 * 4]);
        }
#pragma unroll
        for (int r = 0; r < 4; r++) {
            int k = b_k + r * 8;
            cp16(Bs + (uint32_t)(k * BS_STRIDE + b_n4 * 4) * 4,
                 &W[(size_t)(k0 + k) * Ntot + bcol + b_n4 * 4]);
        }
    };

    issue(0, 0);
    CP_COMMIT();

    for (int ic = 0; ic < 32; ic++) {
        const int s = ic & 1;
        if (ic + 1 < 32) {
            issue(ic + 1, s ^ 1);
            CP_COMMIT();
            CP_WAIT1();
        } else {
            CP_WAIT0();
        }
        __syncthreads();

        const float* Asf = (const float*)(smem + (size_t)s * STAGE_BYTES);
        const float* Bsf = (const float*)(smem + (size_t)s * STAGE_BYTES + AS_BYTES);

#pragma unroll
        for (int ks = 0; ks < 4; ks++) {
            const int kk = ks * 8 + tig;
            float af[4][4], bf[4][2];
#pragma unroll
            for (int mt = 0; mt < 4; mt++) {
                const int row = mw * 64 + mt * 16 + g;
                af[mt][0] = Asf[row * AS_STRIDE + kk];
                af[mt][1] = Asf[(row + 8) * AS_STRIDE + kk];
                af[mt][2] = Asf[row * AS_STRIDE + kk + 4];
                af[mt][3] = Asf[(row + 8) * AS_STRIDE + kk + 4];
            }
#pragma unroll
            for (int nt = 0; nt < 4; nt++) {
                const int col = nw * 32 + nt * 8 + g;
                bf[nt][0] = Bsf[kk * BS_STRIDE + col];
                bf[nt][1] = Bsf[(kk + 4) * BS_STRIDE + col];
            }
#pragma unroll
            for (int mt = 0; mt < 4; mt++)
#pragma unroll
                for (int nt = 0; nt < 4; nt++)
                    mma_tf32(acc[mt][nt], af[mt], bf[nt]);
        }
        __syncthreads();
    }

#pragma unroll
    for (int mt = 0; mt < 4; mt++) {
#pragma unroll
        for (int half = 0; half < 2; half++) {
            const int m = brow + mw * 64 + mt * 16 + g + half * 8;
            const int b = m >> 11, t = m & 2047;
#pragma unroll
            for (int nt = 0; nt < 4; nt++) {
                const int col = bcol + nw * 32 + nt * 8 + 2 * tig;
                float2 o;
                o.x = acc[mt][nt][half * 2 + 0] + bias[col];
                o.y = acc[mt][nt][half * 2 + 1] + bias[col + 1];
                if (MODE == 0) {
                    o.x = to_tf32(o.x); o.y = to_tf32(o.y);  // pre-round for flash
                    const int seg = col >> 10;
                    const int dc  = col & 1023;
                    const int h = dc >> 6, hd = dc & 63;
                    float* dst = (seg == 0) ? g_q : (seg == 1 ? g_k : g_v);
                    *(float2*)&dst[((size_t)((b * NHEAD + h) * TLEN + t)) * HDIM + hd] = o;
                } else {
                    *(float2*)&out[(size_t)m * DMODEL + col] = o;
                }
            }
        }
    }
}

// ---------------------------------------------------------------------------
// Flash attention, causal, tensor-core (m16n8k8 tf32).
// Inputs already tf32-rounded; no cvt on Q/K/V path. Q a-frags hoisted.
// ---------------------------------------------------------------------------
#define FSTRIDE 68
#define FLASH_SMEM ((128*FSTRIDE + 64*FSTRIDE + 64*FSTRIDE + 128*FSTRIDE) * 4)  // 104448

__global__ __launch_bounds__(256, 2) void flash_attn_mma() {
    extern __shared__ float sm[];
    float* Qs = sm;                       // [128][68]
    float* Ks = sm + 128 * FSTRIDE;       // [64][68]  ([kv][hd])
    float* Vs = Ks + 64 * FSTRIDE;        // [64][68]  ([kv][hd])
    float* Ps = Vs + 64 * FSTRIDE;        // [128][68]

    const int tid  = threadIdx.x;
    const int lane = tid & 31;
    const int warp = tid >> 5;
    const int g    = lane >> 2;
    const int tig  = lane & 3;
    const int qt = (int)gridDim.x - 1 - (int)blockIdx.x;
    const int bh = blockIdx.y;
    const int q0 = qt * 128;

    const float* Qg = g_q + (size_t)bh * TLEN * HDIM;
    const float* Kg = g_k + (size_t)bh * TLEN * HDIM;
    const float* Vg = g_v + (size_t)bh * TLEN * HDIM;

    // Load Q block once (already tf32; *0.125 is exact)
#pragma unroll
    for (int r = 0; r < 8; r++) {
        int idx = tid + r * 256;
        int row = idx >> 4, c4 = idx & 15;
        float4 v = *(const float4*)&Qg[(size_t)(q0 + row) * HDIM + c4 * 4];
        v.x *= 0.125f; v.y *= 0.125f; v.z *= 0.125f; v.w *= 0.125f;
        *(float4*)&Qs[row * FSTRIDE + c4 * 4] = v;
    }
    __syncthreads();

    const int qrow_w = q0 + warp * 16;
    const int prow   = warp * 16 + g;

    // Hoist Q a-fragments (invariant across KV tiles)
    float aq[8][4];
#pragma unroll
    for (int ks = 0; ks < 8; ks++) {
        aq[ks][0] = Qs[prow * FSTRIDE + ks * 8 + tig];
        aq[ks][1] = Qs[(prow + 8) * FSTRIDE + ks * 8 + tig];
        aq[ks][2] = Qs[prow * FSTRIDE + ks * 8 + tig + 4];
        aq[ks][3] = Qs[(prow + 8) * FSTRIDE + ks * 8 + tig + 4];
    }

    float m0 = -1e30f, m1 = -1e30f, l0 = 0.f, l1 = 0.f;
    float o[8][4];
#pragma unroll
    for (int nt = 0; nt < 8; nt++)
#pragma unroll
        for (int q = 0; q < 4; q++) o[nt][q] = 0.f;

    const int njt = 2 * qt + 2;

    for (int jt = 0; jt < njt; jt++) {
        __syncthreads();
        const int k0 = jt * 64;
#pragma unroll
        for (int r = 0; r < 4; r++) {
            int idx = tid + r * 256;
            int row = idx >> 4, c4 = idx & 15;
            float4 kv4 = *(const float4*)&Kg[(size_t)(k0 + row) * HDIM + c4 * 4];
            *(float4*)&Ks[row * FSTRIDE + c4 * 4] = kv4;
            float4 vv4 = *(const float4*)&Vg[(size_t)(k0 + row) * HDIM + c4 * 4];
            *(float4*)&Vs[row * FSTRIDE + c4 * 4] = vv4;
        }
        __syncthreads();

        if (qrow_w + 15 < k0) continue;

        // ----- S = Q @ K^T -----
        float s[8][4];
#pragma unroll
        for (int nt = 0; nt < 8; nt++)
#pragma unroll
            for (int q = 0; q < 4; q++) s[nt][q] = 0.f;
#pragma unroll
        for (int ks = 0; ks < 8; ks++) {
#pragma unroll
            for (int nt = 0; nt < 8; nt++) {
                float b[2];
                b[0] = Ks[(nt * 8 + g) * FSTRIDE + ks * 8 + tig];
                b[1] = Ks[(nt * 8 + g) * FSTRIDE + ks * 8 + tig + 4];
                mma_tf32(s[nt], aq[ks], b);
            }
        }

        // ----- causal mask -----
        if (k0 + 63 > qrow_w) {
            const int row0 = qrow_w + g, row1 = row0 + 8;
#pragma unroll
            for (int nt = 0; nt < 8; nt++) {
                const int col = k0 + nt * 8 + 2 * tig;
                if (col     > row0) s[nt][0] = -1e30f;
                if (col + 1 > row0) s[nt][1] = -1e30f;
                if (col     > row1) s[nt][2] = -1e30f;
                if (col + 1 > row1) s[nt][3] = -1e30f;
            }
        }

        // ----- online softmax -----
        float rm0 = -1e30f, rm1 = -1e30f;
#pragma unroll
        for (int nt = 0; nt < 8; nt++) {
            rm0 = fmaxf(rm0, fmaxf(s[nt][0], s[nt][1]));
            rm1 = fmaxf(rm1, fmaxf(s[nt][2], s[nt][3]));
        }
        rm0 = fmaxf(rm0, __shfl_xor_sync(0xffffffffu, rm0, 1));
        rm0 = fmaxf(rm0, __shfl_xor_sync(0xffffffffu, rm0, 2));
        rm1 = fmaxf(rm1, __shfl_xor_sync(0xffffffffu, rm1, 1));
        rm1 = fmaxf(rm1, __shfl_xor_sync(0xffffffffu, rm1, 2));
        const float mn0 = fmaxf(m0, rm0), mn1 = fmaxf(m1, rm1);
        const float c0 = __expf(m0 - mn0), c1 = __expf(m1 - mn1);
        float rs0 = 0.f, rs1 = 0.f;
#pragma unroll
        for (int nt = 0; nt < 8; nt++) {
            float p00 = __expf(s[nt][0] - mn0);
            float p01 = __expf(s[nt][1] - mn0);
            float p10 = __expf(s[nt][2] - mn1);
            float p11 = __expf(s[nt][3] - mn1);
            rs0 += p00 + p01;
            rs1 += p10 + p11;
            float2 w0 = make_float2(to_tf32(p00), to_tf32(p01));
            float2 w1 = make_float2(to_tf32(p10), to_tf32(p11));
            *(float2*)&Ps[prow * FSTRIDE + nt * 8 + 2 * tig] = w0;
            *(float2*)&Ps[(prow + 8) * FSTRIDE + nt * 8 + 2 * tig] = w1;
            o[nt][0] *= c0; o[nt][1] *= c0;
            o[nt][2] *= c1; o[nt][3] *= c1;
        }
        rs0 += __shfl_xor_sync(0xffffffffu, rs0, 1);
        rs0 += __shfl_xor_sync(0xffffffffu, rs0, 2);
        rs1 += __shfl_xor_sync(0xffffffffu, rs1, 1);
        rs1 += __shfl_xor_sync(0xffffffffu, rs1, 2);
        l0 = l0 * c0 + rs0; m0 = mn0;
        l1 = l1 * c1 + rs1; m1 = mn1;

        __syncwarp();

        // ----- O += P @ V -----
#pragma unroll
        for (int ks = 0; ks < 8; ks++) {
            float a[4];
            a[0] = Ps[prow * FSTRIDE + ks * 8 + tig];
            a[1] = Ps[(prow + 8) * FSTRIDE + ks * 8 + tig];
            a[2] = Ps[prow * FSTRIDE + ks * 8 + tig + 4];
            a[3] = Ps[(prow + 8) * FSTRIDE + ks * 8 + tig + 4];
#pragma unroll
            for (int nt = 0; nt < 8; nt++) {
                float b[2];
                b[0] = Vs[(ks * 8 + tig) * FSTRIDE + nt * 8 + g];
                b[1] = Vs[(ks * 8 + tig + 4) * FSTRIDE + nt * 8 + g];
                mma_tf32(o[nt], a, b);
            }
        }
    }

    // ----- normalize + write [B,T,D], tf32-rounded for out-proj -----
    const int b = bh >> 4;
    const int h = bh & 15;
    const float inv0 = 1.0f / l0, inv1 = 1.0f / l1;
    const int row0 = qrow_w + g;
#pragma unroll
    for (int nt = 0; nt < 8; nt++) {
        const int col = h * HDIM + nt * 8 + 2 * tig;
        float2 v0 = make_float2(to_tf32(o[nt][0] * inv0), to_tf32(o[nt][1] * inv0));
        float2 v1 = make_float2(to_tf32(o[nt][2] * inv1), to_tf32(o[nt][3] * inv1));
        *(float2*)&g_ao[(size_t)(b * TLEN + row0) * DMODEL + col] = v0;
        *(float2*)&g_ao[(size_t)(b * TLEN + row0 + 8) * DMODEL + col] = v1;
    }
}

// ---------------------------------------------------------------------------
extern "C" void kernel_launch(void* const* d_in, const int* in_sizes, int n_in,
                              void* d_out, int out_size) {
    const float* x     = (const float*)d_in[0];
    const float* W_qkv = (const float*)d_in[1];
    const float* b_qkv = (const float*)d_in[2];
    const float* W_out = (const float*)d_in[3];
    const float* b_out = (const float*)d_in[4];
    float* out = (float*)d_out;

    cudaFuncSetAttribute(gemm_mma<0>, cudaFuncAttributeMaxDynamicSharedMemorySize, GEMM_SMEM);
    cudaFuncSetAttribute(gemm_mma<1>, cudaFuncAttributeMaxDynamicSharedMemorySize, GEMM_SMEM);
    cudaFuncSetAttribute(flash_attn_mma, cudaFuncAttributeMaxDynamicSharedMemorySize, FLASH_SMEM);

    float* xr;   cudaGetSymbolAddress((void**)&xr,   g_xr);
    float* wq;   cudaGetSymbolAddress((void**)&wq,   g_wqkv);
    float* wo;   cudaGetSymbolAddress((void**)&wo,   g_wout);

    const int n4x = MTOT * DMODEL / 4;          // 2097152
    const int n4q = DMODEL * 3 * DMODEL / 4;    // 786432
    const int n4o = DMODEL * DMODEL / 4;        // 262144
    round_tf32<<<(n4x + 255) / 256, 256>>>((const float4*)x,     (float4*)xr, n4x);
    round_tf32<<<(n4q + 255) / 256, 256>>>((const float4*)W_qkv, (float4*)wq, n4q);
    round_tf32<<<(n4o + 255) / 256, 256>>>((const float4*)W_out, (float4*)wo, n4o);

    gemm_mma<0><<<dim3(3 * DMODEL / 128, MTOT / 128), 256, GEMM_SMEM>>>(
        b_qkv, nullptr, 3 * DMODEL);
    flash_attn_mma<<<dim3(TLEN / 128, BATCH * NHEAD), 256, FLASH_SMEM>>>();
    gemm_mma<1><<<dim3(DMODEL / 128, MTOT / 128), 256, GEMM_SMEM>>>(
        b_out, out, DMODEL);
}